// round 7
// baseline (speedup 1.0000x reference)
#include <cuda_runtime.h>
#include <cuda_fp16.h>
#include <cstdint>

// ---------------------------------------------------------------------------
// GraphSage (eval) on GB300 — round 7: fused-norm conv GEMM (128x256 tile),
// warp-per-node fp16 aggregation, batched weight conversion.
// ---------------------------------------------------------------------------

#define NMAX 50000
#define EMAX 1000000
#define FDIM 256
#define PADC 304

// fp32 buffers
__device__ __align__(16) float g_h[NMAX * FDIM];
// fp16 buffers (zero-initialized; pad columns of c16/wp1/wp2 never written)
__device__ __align__(16) __half g_h16[NMAX * FDIM];
__device__ __align__(16) __half g_hn16[NMAX * FDIM];
__device__ __align__(16) __half g_hagg16[NMAX * FDIM];
__device__ __align__(16) __half g_tmp16[NMAX * PADC];
__device__ __align__(16) __half g_emb16[(NMAX + 1) * 64];
__device__ __align__(16) __half g_c16[NMAX * PADC];
__device__ __align__(16) __half g_we16[256 * 64];
__device__ __align__(16) __half g_wp1[304 * PADC];
__device__ __align__(16) __half g_wp2[256 * PADC];
__device__ __align__(16) __half g_wc16[3 * 256 * 512];
__device__ __align__(16) __half g_wo1[2 * 256 * 256];
__device__ __align__(16) __half g_wo2[2 * 256 * 256];
// CSR
__device__ int g_deg[NMAX];
__device__ int g_rowoff[NMAX + 1];
__device__ int g_cursor[NMAX];
__device__ int g_adj[EMAX];

// ---------------------------------------------------------------------------
// One fused fp32->fp16 conversion kernel for all inputs/weights.
__global__ void cvt_all_kernel(
    const float* emb, const float* content, const float* W_exp,
    const float* W_p1, const float* W_p2, const float* W_conv,
    const float* Wo1, const float* Wo2,
    __half* d_emb, __half* d_c, __half* d_we, __half* d_wp1, __half* d_wp2,
    __half* d_wc, __half* d_wo1, __half* d_wo2,
    int N, int NC, int ED, int F, int L)
{
    const int s0 = (N + 1) * ED;          // emb (flat)
    const int s1 = N * NC;                // content (300 -> 304)
    const int s2 = F * ED;                // W_exp (flat)
    const int s3 = NC * NC;               // W_p1 (300 -> 304)
    const int s4 = F * NC;                // W_p2 (300 -> 304)
    const int s5 = L * F * 2 * F;         // W_conv (flat)
    const int s6 = (L - 1) * F * F;       // Wo1 (flat)
    const int s7 = (L - 1) * F * F;       // Wo2 (flat)
    const int total = s0 + s1 + s2 + s3 + s4 + s5 + s6 + s7;
    for (int i = blockIdx.x * blockDim.x + threadIdx.x; i < total;
         i += gridDim.x * blockDim.x) {
        int j = i;
        if (j < s0) { d_emb[j] = __float2half_rn(emb[j]); continue; }
        j -= s0;
        if (j < s1) {
            int r = j / NC, c = j - r * NC;
            d_c[r * PADC + c] = __float2half_rn(content[j]);
            continue;
        }
        j -= s1;
        if (j < s2) { d_we[j] = __float2half_rn(W_exp[j]); continue; }
        j -= s2;
        if (j < s3) {
            int r = j / NC, c = j - r * NC;
            d_wp1[r * PADC + c] = __float2half_rn(W_p1[j]);
            continue;
        }
        j -= s3;
        if (j < s4) {
            int r = j / NC, c = j - r * NC;
            d_wp2[r * PADC + c] = __float2half_rn(W_p2[j]);
            continue;
        }
        j -= s4;
        if (j < s5) { d_wc[j] = __float2half_rn(W_conv[j]); continue; }
        j -= s5;
        if (j < s6) { d_wo1[j] = __float2half_rn(Wo1[j]); continue; }
        j -= s6;
        d_wo2[j] = __float2half_rn(Wo2[j]);
    }
}

// ---------------------------------------------------------------------------
// CSR build
__global__ void zero_deg_kernel(int n) {
    int i = blockIdx.x * blockDim.x + threadIdx.x;
    if (i < n) g_deg[i] = 0;
}
__global__ void count_deg_kernel(const int* __restrict__ dst, int E) {
    int i = blockIdx.x * blockDim.x + threadIdx.x;
    int stride = gridDim.x * blockDim.x;
    for (; i < E; i += stride) atomicAdd(&g_deg[dst[i]], 1);
}
__global__ void scan_kernel(int n) {
    __shared__ int warp_sums[32];
    __shared__ int s_carry;
    int t = threadIdx.x;
    if (t == 0) s_carry = 0;
    __syncthreads();
    for (int base = 0; base < n; base += 1024) {
        int i = base + t;
        int v = (i < n) ? g_deg[i] : 0;
        int x = v;
        #pragma unroll
        for (int off = 1; off < 32; off <<= 1) {
            int y = __shfl_up_sync(0xffffffffu, x, off);
            if ((t & 31) >= off) x += y;
        }
        if ((t & 31) == 31) warp_sums[t >> 5] = x;
        __syncthreads();
        if (t < 32) {
            int w = warp_sums[t];
            int xx = w;
            #pragma unroll
            for (int off = 1; off < 32; off <<= 1) {
                int y = __shfl_up_sync(0xffffffffu, xx, off);
                if (t >= off) xx += y;
            }
            warp_sums[t] = xx - w;
        }
        __syncthreads();
        int incl = x + warp_sums[t >> 5];
        int excl = incl - v + s_carry;
        if (i < n) { g_rowoff[i] = excl; g_cursor[i] = excl; }
        __syncthreads();
        if (t == 1023) s_carry += incl;
        __syncthreads();
    }
    if (t == 0) g_rowoff[n] = s_carry;
}
__global__ void scatter_kernel(const int* __restrict__ src,
                               const int* __restrict__ dst, int E) {
    int i = blockIdx.x * blockDim.x + threadIdx.x;
    int stride = gridDim.x * blockDim.x;
    for (; i < E; i += stride) {
        int p = atomicAdd(&g_cursor[dst[i]], 1);
        g_adj[p] = src[i];
    }
}

// aggregate: hagg16[n] = fp16(mean over in-neighbors of h16)
// one warp per node; thread j owns 8 halves (16B) at col j*8; 2-edge unroll.
__global__ void aggregate_kernel(int N) {
    int node = blockIdx.x * blockDim.y + threadIdx.y;
    if (node >= N) return;
    int j = threadIdx.x;  // 0..31
    int beg = g_rowoff[node], end = g_rowoff[node + 1];
    float acc[8];
    #pragma unroll
    for (int q = 0; q < 8; q++) acc[q] = 0.f;
    int e = beg;
    for (; e + 1 < end; e += 2) {
        int s0 = g_adj[e], s1 = g_adj[e + 1];
        uint4 u0 = *(const uint4*)&g_h16[(size_t)s0 * FDIM + j * 8];
        uint4 u1 = *(const uint4*)&g_h16[(size_t)s1 * FDIM + j * 8];
        const __half2* p0 = (const __half2*)&u0;
        const __half2* p1 = (const __half2*)&u1;
        #pragma unroll
        for (int q = 0; q < 4; q++) {
            float2 a = __half22float2(p0[q]);
            float2 b = __half22float2(p1[q]);
            acc[2 * q] += a.x + b.x;
            acc[2 * q + 1] += a.y + b.y;
        }
    }
    if (e < end) {
        int s0 = g_adj[e];
        uint4 u0 = *(const uint4*)&g_h16[(size_t)s0 * FDIM + j * 8];
        const __half2* p0 = (const __half2*)&u0;
        #pragma unroll
        for (int q = 0; q < 4; q++) {
            float2 a = __half22float2(p0[q]);
            acc[2 * q] += a.x;
            acc[2 * q + 1] += a.y;
        }
    }
    int d = end - beg;
    float inv = 1.0f / (float)(d > 1 ? d : 1);
    uint4 o;
    __half2* po = (__half2*)&o;
    #pragma unroll
    for (int q = 0; q < 4; q++)
        po[q] = __floats2half2_rn(acc[2 * q] * inv, acc[2 * q + 1] * inv);
    *(uint4*)&g_hagg16[(size_t)node * FDIM + j * 8] = o;
}

// ---------------------------------------------------------------------------
// shared MMA helpers
__device__ __forceinline__ void mma_f16(float* c, const uint32_t* a,
                                        const uint32_t* b) {
    asm volatile(
        "mma.sync.aligned.m16n8k16.row.col.f32.f16.f16.f32 "
        "{%0,%1,%2,%3}, {%4,%5,%6,%7}, {%8,%9}, {%0,%1,%2,%3};"
        : "+f"(c[0]), "+f"(c[1]), "+f"(c[2]), "+f"(c[3])
        : "r"(a[0]), "r"(a[1]), "r"(a[2]), "r"(a[3]), "r"(b[0]), "r"(b[1]));
}
__device__ __forceinline__ void ldsm4(uint32_t* r, uint32_t addr) {
    asm volatile("ldmatrix.sync.aligned.m8n8.x4.shared.b16 {%0,%1,%2,%3}, [%4];"
                 : "=r"(r[0]), "=r"(r[1]), "=r"(r[2]), "=r"(r[3]) : "r"(addr));
}
__device__ __forceinline__ void cp16(uint32_t dst, const void* src, int nbytes) {
    asm volatile("cp.async.cg.shared.global [%0], [%1], 16, %2;"
                 :: "r"(dst), "l"(src), "r"(nbytes) : "memory");
}
__device__ __forceinline__ void cp_commit() {
    asm volatile("cp.async.commit_group;" ::: "memory");
}
__device__ __forceinline__ void cp_wait1() {
    asm volatile("cp.async.wait_group 1;" ::: "memory");
}

// ---------------------------------------------------------------------------
// Generic fp16 GEMM (round 6): CTA 128x128, K-chunk 64, 3-stage.
#define GBM 128
#define GBN 128
#define GBK 64
#define TILE_BYTES 16384
#define STAGE_BYTES (2 * TILE_BYTES)
#define NSTAGE 3

extern __shared__ __align__(16) char sm_raw[];

__global__ __launch_bounds__(256, 2)
void gemm_f16(const __half* __restrict__ A, const __half* __restrict__ A2,
              int kSplit, int lda,
              const int* __restrict__ gidx,
              const __half* __restrict__ W, int ldw,
              const float* __restrict__ bias,
              const float* __restrict__ addsrc,
              float* __restrict__ C, __half* __restrict__ C16, int ldc,
              int M, int Ncols, int K, int act)
{
    const int tid = threadIdx.x;
    const int wid = tid >> 5;
    const int lane = tid & 31;
    const int bm = blockIdx.x * GBM;
    const int bn = blockIdx.y * GBN;
    const int warp_m = (wid >> 2) * 64;
    const int warp_n = (wid & 3) * 32;

    const int ldRow = tid >> 1;
    const int kHalf = tid & 1;

    const bool aValid = (bm + ldRow < M);
    int aR = aValid ? (bm + ldRow) : 0;
    if (gidx) aR = __ldg(&gidx[aValid ? bm + ldRow : 0]);
    const __half* aBase = A + (size_t)aR * lda;
    const __half* aBase2 = A2 ? (A2 + (size_t)aR * lda) : nullptr;
    const bool bValid = (bn + ldRow < Ncols);
    const __half* bBase = W + (size_t)(bValid ? bn + ldRow : 0) * ldw;

    const uint32_t smemBase = (uint32_t)__cvta_generic_to_shared(sm_raw);
    const int nCh = (K + GBK - 1) / GBK;
    const int ldSwz = (ldRow & 7);

    float acc[4][4][4];
    #pragma unroll
    for (int mt = 0; mt < 4; mt++)
        #pragma unroll
        for (int nt = 0; nt < 4; nt++)
            #pragma unroll
            for (int j = 0; j < 4; j++) acc[mt][nt][j] = 0.f;

    auto issueStage = [&](int ch, int stage) {
        if (ch < nCh) {
            const uint32_t aDst = smemBase + stage * STAGE_BYTES + ldRow * 128;
            const uint32_t bDst = aDst + TILE_BYTES;
            #pragma unroll
            for (int j = 0; j < 4; j++) {
                const int c = kHalf * 4 + j;
                const int k = ch * GBK + c * 8;
                const int rem = K - k;
                const int nb = (rem >= 8) ? 16 : (rem > 0 ? rem * 2 : 0);
                const __half* ap = (k < kSplit) ? (aBase + k)
                                                : (aBase2 + (k - kSplit));
                const uint32_t sw = (uint32_t)((c ^ ldSwz) << 4);
                cp16(aDst + sw, ap, aValid ? nb : 0);
                cp16(bDst + sw, bBase + k, bValid ? nb : 0);
            }
        }
        cp_commit();
    };

    const int l8 = lane & 7;
    int aRowB[4], aSwz[4];
    #pragma unroll
    for (int mt = 0; mt < 4; mt++) {
        int row = warp_m + mt * 16 + l8 + ((lane >> 3) & 1) * 8;
        aRowB[mt] = row * 128;
        aSwz[mt] = row & 7;
    }
    const int aColAdd = lane >> 4;
    int bRowB[2], bSwz[2];
    #pragma unroll
    for (int pr = 0; pr < 2; pr++) {
        int row = warp_n + pr * 16 + l8 + ((lane >> 4) & 1) * 8;
        bRowB[pr] = row * 128;
        bSwz[pr] = row & 7;
    }
    const int bColAdd = (lane >> 3) & 1;

    auto computeStage = [&](int stage) {
        const uint32_t aTile = smemBase + stage * STAGE_BYTES;
        const uint32_t bTile = aTile + TILE_BYTES;
        #pragma unroll
        for (int ks = 0; ks < 4; ks++) {
            uint32_t af[4][4], bf[4][2];
            const int colA = ks * 2 + aColAdd;
            #pragma unroll
            for (int mt = 0; mt < 4; mt++)
                ldsm4(af[mt], aTile + aRowB[mt] + ((colA ^ aSwz[mt]) << 4));
            const int colB = ks * 2 + bColAdd;
            #pragma unroll
            for (int pr = 0; pr < 2; pr++) {
                uint32_t r[4];
                ldsm4(r, bTile + bRowB[pr] + ((colB ^ bSwz[pr]) << 4));
                bf[2 * pr][0] = r[0]; bf[2 * pr][1] = r[1];
                bf[2 * pr + 1][0] = r[2]; bf[2 * pr + 1][1] = r[3];
            }
            #pragma unroll
            for (int mt = 0; mt < 4; mt++)
                #pragma unroll
                for (int nt = 0; nt < 4; nt++)
                    mma_f16(acc[mt][nt], af[mt], bf[nt]);
        }
    };

    issueStage(0, 0);
    issueStage(1, 1);
    for (int ch = 0; ch < nCh; ch++) {
        cp_wait1();
        __syncthreads();
        computeStage(ch % NSTAGE);
        issueStage(ch + 2, (ch + 2) % NSTAGE);
    }

    #pragma unroll
    for (int mt = 0; mt < 4; mt++) {
        int row = bm + warp_m + mt * 16 + (lane >> 2);
        #pragma unroll
        for (int nt = 0; nt < 4; nt++) {
            int col = bn + warp_n + nt * 8 + 2 * (lane & 3);
            if (col >= Ncols) continue;
            float b0 = __ldg(&bias[col]);
            float b1 = __ldg(&bias[col + 1]);
            #pragma unroll
            for (int half = 0; half < 2; half++) {
                int r = row + half * 8;
                if (r >= M) continue;
                float v0 = acc[mt][nt][half * 2 + 0] + b0;
                float v1 = acc[mt][nt][half * 2 + 1] + b1;
                if (act) {
                    v0 = (v0 > 0.f) ? v0 : 0.1f * v0;
                    v1 = (v1 > 0.f) ? v1 : 0.1f * v1;
                }
                if (addsrc) {
                    const float2 s = *(const float2*)&addsrc[(size_t)r * ldc + col];
                    v0 += s.x; v1 += s.y;
                }
                if (C)
                    *(float2*)&C[(size_t)r * ldc + col] = make_float2(v0, v1);
                if (C16)
                    *(__half2*)&C16[(size_t)r * ldc + col] =
                        __floats2half2_rn(v0, v1);
            }
        }
    }
}

// ---------------------------------------------------------------------------
// Conv GEMM with fused row L2-norm: CTA 128x256 (full row), 512 threads,
// 16 warps of 32x64, K-chunk 64, 2-stage pipeline (A 16KB + B 32KB per stage).
// out = l2norm_row( act( [h16|hagg16] @ Wc^T + bc ) ), fp16 or fp32 out.
#define CV_ABYTES 16384              // 128 x 128B
#define CV_BBYTES 32768              // 256 x 128B
#define CV_STAGE (CV_ABYTES + CV_BBYTES)

__global__ __launch_bounds__(512, 2)
void gemm_conv(const __half* __restrict__ A, const __half* __restrict__ A2,
               int kSplit,
               const __half* __restrict__ W,
               const float* __restrict__ bias,
               float* __restrict__ C, __half* __restrict__ C16,
               int M, int K, int act)
{
    const int tid = threadIdx.x;
    const int wid = tid >> 5;
    const int lane = tid & 31;
    const int bm = blockIdx.x * 128;
    const int warp_m = (wid >> 2) * 32;   // 0,32,64,96
    const int warp_n = (wid & 3) * 64;    // 0,64,128,192

    // loader roles
    const int aRow = tid >> 2, aq = tid & 3;       // A: 2 cp16 (cols aq*2, +1)
    const int bRow = tid >> 1, bh = tid & 1;       // B: 4 cp16 (cols bh*4+j)
    const bool aValid = (bm + aRow < M);
    const __half* aBase = A + (size_t)(aValid ? bm + aRow : 0) * K / 2 * 2;
    // NOTE: lda == kSplit for both halves (h16/hagg16 are [_,256], K=512)
    const __half* aBaseLo = A + (size_t)(aValid ? bm + aRow : 0) * kSplit;
    const __half* aBaseHi = A2 + (size_t)(aValid ? bm + aRow : 0) * kSplit;
    const __half* bBase = W + (size_t)bRow * K;

    const uint32_t smemBase = (uint32_t)__cvta_generic_to_shared(sm_raw);
    const int nCh = K / GBK;               // K = 512 -> 8
    const int aSwzL = aRow & 7, bSwzL = bRow & 7;

    float acc[2][8][4];
    #pragma unroll
    for (int mt = 0; mt < 2; mt++)
        #pragma unroll
        for (int nt = 0; nt < 8; nt++)
            #pragma unroll
            for (int j = 0; j < 4; j++) acc[mt][nt][j] = 0.f;

    auto issueStage = [&](int ch, int stage) {
        if (ch < nCh) {
            const uint32_t aDst = smemBase + stage * CV_STAGE + aRow * 128;
            const uint32_t bDst = smemBase + stage * CV_STAGE + CV_ABYTES + bRow * 128;
            #pragma unroll
            for (int j = 0; j < 2; j++) {
                const int c = aq * 2 + j;
                const int k = ch * GBK + c * 8;
                const __half* ap = (k < kSplit) ? (aBaseLo + k)
                                                : (aBaseHi + (k - kSplit));
                cp16(aDst + ((c ^ aSwzL) << 4), ap, aValid ? 16 : 0);
            }
            #pragma unroll
            for (int j = 0; j < 4; j++) {
                const int c = bh * 4 + j;
                const int k = ch * GBK + c * 8;
                cp16(bDst + ((c ^ bSwzL) << 4), bBase + k, 16);
            }
        }
        cp_commit();
    };

    const int l8 = lane & 7;
    int aRowB[2], aSwz[2];
    #pragma unroll
    for (int mt = 0; mt < 2; mt++) {
        int row = warp_m + mt * 16 + l8 + ((lane >> 3) & 1) * 8;
        aRowB[mt] = row * 128;
        aSwz[mt] = row & 7;
    }
    const int aColAdd = lane >> 4;
    int bRowB[4], bSwz[4];
    #pragma unroll
    for (int pr = 0; pr < 4; pr++) {
        int row = warp_n + pr * 16 + l8 + ((lane >> 4) & 1) * 8;
        bRowB[pr] = row * 128;
        bSwz[pr] = row & 7;
    }
    const int bColAdd = (lane >> 3) & 1;

    auto computeStage = [&](int stage) {
        const uint32_t aTile = smemBase + stage * CV_STAGE;
        const uint32_t bTile = aTile + CV_ABYTES;
        #pragma unroll
        for (int ks = 0; ks < 4; ks++) {
            uint32_t af[2][4], bf[8][2];
            const int colA = ks * 2 + aColAdd;
            #pragma unroll
            for (int mt = 0; mt < 2; mt++)
                ldsm4(af[mt], aTile + aRowB[mt] + ((colA ^ aSwz[mt]) << 4));
            const int colB = ks * 2 + bColAdd;
            #pragma unroll
            for (int pr = 0; pr < 4; pr++) {
                uint32_t r[4];
                ldsm4(r, bTile + bRowB[pr] + ((colB ^ bSwz[pr]) << 4));
                bf[2 * pr][0] = r[0]; bf[2 * pr][1] = r[1];
                bf[2 * pr + 1][0] = r[2]; bf[2 * pr + 1][1] = r[3];
            }
            #pragma unroll
            for (int mt = 0; mt < 2; mt++)
                #pragma unroll
                for (int nt = 0; nt < 8; nt++)
                    mma_f16(acc[mt][nt], af[mt], bf[nt]);
        }
    };

    // 2-stage pipeline
    issueStage(0, 0);
    issueStage(1, 1);
    for (int ch = 0; ch < nCh; ch++) {
        cp_wait1();
        __syncthreads();
        computeStage(ch & 1);
        __syncthreads();
        issueStage(ch + 2, ch & 1);
    }

    // ---- fused epilogue: bias + act, row L2 norm via smem, store ----
    float* ssrow = (float*)sm_raw;   // 128 floats (pipeline done)
    __syncthreads();
    if (tid < 128) ssrow[tid] = 0.f;
    __syncthreads();

    float ssloc[2][2];
    ssloc[0][0] = ssloc[0][1] = ssloc[1][0] = ssloc[1][1] = 0.f;
    #pragma unroll
    for (int mt = 0; mt < 2; mt++) {
        #pragma unroll
        for (int nt = 0; nt < 8; nt++) {
            int col = warp_n + nt * 8 + 2 * (lane & 3);
            float b0 = __ldg(&bias[col]);
            float b1 = __ldg(&bias[col + 1]);
            #pragma unroll
            for (int half = 0; half < 2; half++) {
                float v0 = acc[mt][nt][half * 2 + 0] + b0;
                float v1 = acc[mt][nt][half * 2 + 1] + b1;
                if (act) {
                    v0 = (v0 > 0.f) ? v0 : 0.1f * v0;
                    v1 = (v1 > 0.f) ? v1 : 0.1f * v1;
                }
                acc[mt][nt][half * 2 + 0] = v0;
                acc[mt][nt][half * 2 + 1] = v1;
                ssloc[mt][half] += v0 * v0 + v1 * v1;
            }
        }
    }
    // reduce across the 4 lanes sharing a row (lane&3)
    #pragma unroll
    for (int mt = 0; mt < 2; mt++)
        #pragma unroll
        for (int half = 0; half < 2; half++) {
            float s = ssloc[mt][half];
            s += __shfl_xor_sync(0xffffffffu, s, 1);
            s += __shfl_xor_sync(0xffffffffu, s, 2);
            ssloc[mt][half] = s;
        }
    if ((lane & 3) == 0) {
        #pragma unroll
        for (int mt = 0; mt < 2; mt++)
            #pragma unroll
            for (int half = 0; half < 2; half++)
                atomicAdd(&ssrow[warp_m + mt * 16 + (lane >> 2) + half * 8],
                          ssloc[mt][half]);
    }
    __syncthreads();

    #pragma unroll
    for (int mt = 0; mt < 2; mt++) {
        #pragma unroll
        for (int half = 0; half < 2; half++) {
            int lr = warp_m + mt * 16 + (lane >> 2) + half * 8;
            int r = bm + lr;
            if (r >= M) continue;
            float inv = 1.0f / fmaxf(sqrtf(ssrow[lr]), 1e-6f);
            #pragma unroll
            for (int nt = 0; nt < 8; nt++) {
                int col = warp_n + nt * 8 + 2 * (lane & 3);
                float v0 = acc[mt][nt][half * 2 + 0] * inv;
                float v1 = acc[mt][nt][half * 2 + 1] * inv;
                if (C16)
                    *(__half2*)&C16[(size_t)r * FDIM + col] =
                        __floats2half2_rn(v0, v1);
                else
                    *(float2*)&C[(size_t)r * FDIM + col] = make_float2(v0, v1);
            }
        }
    }
}

// ---------------------------------------------------------------------------
extern "C" void kernel_launch(void* const* d_in, const int* in_sizes, int n_in,
                              void* d_out, int out_size) {
    const int*   node_ids = (const int*)  d_in[0];
    const float* content  = (const float*)d_in[1];
    const int*   src      = (const int*)  d_in[2];
    const int*   dst      = (const int*)  d_in[3];
    const float* emb      = (const float*)d_in[4];
    const float* W_exp    = (const float*)d_in[5];
    const float* b_exp    = (const float*)d_in[6];
    const float* W_p1     = (const float*)d_in[7];
    const float* b_p1     = (const float*)d_in[8];
    const float* W_p2     = (const float*)d_in[9];
    const float* b_p2     = (const float*)d_in[10];
    const float* W_conv   = (const float*)d_in[11];
    const float* b_conv   = (const float*)d_in[12];
    const float* Wo1      = (const float*)d_in[13];
    const float* bo1      = (const float*)d_in[14];
    const float* Wo2      = (const float*)d_in[15];
    const float* bo2      = (const float*)d_in[16];
    float* out = (float*)d_out;

    const int N  = in_sizes[0];
    const int E  = in_sizes[2];
    const int NC = in_sizes[1] / N;                 // 300
    const int ED = in_sizes[4] / (N + 1);           // 64
    const int F  = in_sizes[5] / ED;                // 256
    const int L  = in_sizes[11] / (F * 2 * F);      // 3

    float *p_h;
    __half *p_h16, *p_hn16, *p_hagg16, *p_tmp16, *p_emb16, *p_c16;
    __half *p_we, *p_wp1, *p_wp2, *p_wc, *p_wo1, *p_wo2;
    cudaGetSymbolAddress((void**)&p_h, g_h);
    cudaGetSymbolAddress((void**)&p_h16, g_h16);
    cudaGetSymbolAddress((void**)&p_hn16, g_hn16);
    cudaGetSymbolAddress((void**)&p_hagg16, g_hagg16);
    cudaGetSymbolAddress((void**)&p_tmp16, g_tmp16);
    cudaGetSymbolAddress((void**)&p_emb16, g_emb16);
    cudaGetSymbolAddress((void**)&p_c16, g_c16);
    cudaGetSymbolAddress((void**)&p_we, g_we16);
    cudaGetSymbolAddress((void**)&p_wp1, g_wp1);
    cudaGetSymbolAddress((void**)&p_wp2, g_wp2);
    cudaGetSymbolAddress((void**)&p_wc, g_wc16);
    cudaGetSymbolAddress((void**)&p_wo1, g_wo1);
    cudaGetSymbolAddress((void**)&p_wo2, g_wo2);

    const int SMEM = NSTAGE * STAGE_BYTES;    // 98304
    const int SMEMC = 2 * CV_STAGE;           // 98304
    cudaFuncSetAttribute(gemm_f16, cudaFuncAttributeMaxDynamicSharedMemorySize, SMEM);
    cudaFuncSetAttribute(gemm_conv, cudaFuncAttributeMaxDynamicSharedMemorySize, SMEMC);

    // ---- conversions (one kernel) ----
    cvt_all_kernel<<<2048, 256>>>(emb, content, W_exp, W_p1, W_p2, W_conv,
                                  Wo1, Wo2, p_emb16, p_c16, p_we, p_wp1,
                                  p_wp2, p_wc, p_wo1, p_wo2, N, NC, ED, F, L);

    // ---- CSR build ----
    zero_deg_kernel<<<(N + 255) / 256, 256>>>(N);
    count_deg_kernel<<<1024, 256>>>(dst, E);
    scan_kernel<<<1, 1024>>>(N);
    scatter_kernel<<<1024, 256>>>(src, dst, E);

    const int gmx = (N + GBM - 1) / GBM;
    auto gy = [](int n) { return (n + GBN - 1) / GBN; };
    const int KBIG = 1 << 30;

    // ---- initial representation ----
    gemm_f16<<<dim3(gmx, gy(F)), 256, SMEM>>>(
        p_emb16, nullptr, KBIG, ED, node_ids, p_we, ED, b_exp, nullptr,
        p_h, nullptr, F, N, F, ED, 1);
    gemm_f16<<<dim3(gmx, gy(NC)), 256, SMEM>>>(
        p_c16, nullptr, KBIG, PADC, nullptr, p_wp1, PADC, b_p1, nullptr,
        nullptr, p_tmp16, PADC, N, NC, PADC, 1);
    gemm_f16<<<dim3(gmx, gy(F)), 256, SMEM>>>(
        p_tmp16, nullptr, KBIG, PADC, nullptr, p_wp2, PADC, b_p2, p_h,
        nullptr, p_h16, F, N, F, PADC, 1);

    // ---- layers ----
    for (int i = 0; i < L; i++) {
        dim3 aggBlk(32, 8);
        aggregate_kernel<<<(N + 7) / 8, aggBlk>>>(N);

        int act = (i < L - 1) ? 1 : 0;
        // normed conv output: fp16 hn16 (intermediate) or fp32 out (final)
        gemm_conv<<<gmx, 512, SMEMC>>>(
            p_h16, p_hagg16, F,
            p_wc + (size_t)i * F * 2 * F, b_conv + (size_t)i * F,
            (i == L - 1) ? out : nullptr,
            (i == L - 1) ? nullptr : p_hn16,
            N, 2 * F, act);

        if (i < L - 1) {
            gemm_f16<<<dim3(gmx, gy(F)), 256, SMEM>>>(
                p_hn16, nullptr, KBIG, F, nullptr,
                p_wo1 + (size_t)i * F * F, F,
                bo1 + (size_t)i * F, nullptr,
                nullptr, p_tmp16, F, N, F, F, 1);
            gemm_f16<<<dim3(gmx, gy(F)), 256, SMEM>>>(
                p_tmp16, nullptr, KBIG, F, nullptr,
                p_wo2 + (size_t)i * F * F, F,
                bo2 + (size_t)i * F, nullptr,
                nullptr, p_h16, F, N, F, F, 0);
        }
    }
}

// round 8
// speedup vs baseline: 1.2908x; 1.2908x over previous
#include <cuda_runtime.h>
#include <cuda_fp16.h>
#include <cstdint>

// ---------------------------------------------------------------------------
// GraphSage (eval) on GB300 — round 8: round-6 GEMM structure (877us known
// good) + parallel CSR scan + 4-edge-unrolled aggregation + batched cvt.
// ---------------------------------------------------------------------------

#define NMAX 50000
#define EMAX 1000000
#define FDIM 256
#define PADC 304
#define SCAN_B 1024
#define MAXBLK 64

// fp32 buffers
__device__ __align__(16) float g_h[NMAX * FDIM];
__device__ __align__(16) float g_hn[NMAX * FDIM];
// fp16 buffers (zero-initialized; pad columns never written)
__device__ __align__(16) __half g_h16[NMAX * FDIM];
__device__ __align__(16) __half g_hn16[NMAX * FDIM];
__device__ __align__(16) __half g_hagg16[NMAX * FDIM];
__device__ __align__(16) __half g_tmp16[NMAX * PADC];
__device__ __align__(16) __half g_emb16[(NMAX + 1) * 64];
__device__ __align__(16) __half g_c16[NMAX * PADC];
__device__ __align__(16) __half g_we16[256 * 64];
__device__ __align__(16) __half g_wp1[304 * PADC];
__device__ __align__(16) __half g_wp2[256 * PADC];
__device__ __align__(16) __half g_wc16[3 * 256 * 512];
__device__ __align__(16) __half g_wo1[2 * 256 * 256];
__device__ __align__(16) __half g_wo2[2 * 256 * 256];
// CSR
__device__ int g_deg[NMAX];
__device__ int g_rowoff[NMAX + 1];
__device__ int g_cursor[NMAX];
__device__ int g_adj[EMAX];
__device__ int g_bsum[MAXBLK];
__device__ int g_boff[MAXBLK];

// ---------------------------------------------------------------------------
// Batched fp32 -> fp16 conversion for all inputs/weights.
__global__ void cvt_all_kernel(
    const float* emb, const float* content, const float* W_exp,
    const float* W_p1, const float* W_p2, const float* W_conv,
    const float* Wo1, const float* Wo2,
    __half* d_emb, __half* d_c, __half* d_we, __half* d_wp1, __half* d_wp2,
    __half* d_wc, __half* d_wo1, __half* d_wo2,
    int N, int NC, int ED, int F, int L)
{
    const int s0 = (N + 1) * ED;
    const int s1 = N * NC;
    const int s2 = F * ED;
    const int s3 = NC * NC;
    const int s4 = F * NC;
    const int s5 = L * F * 2 * F;
    const int s6 = (L - 1) * F * F;
    const int s7 = (L - 1) * F * F;
    const int total = s0 + s1 + s2 + s3 + s4 + s5 + s6 + s7;
    for (int i = blockIdx.x * blockDim.x + threadIdx.x; i < total;
         i += gridDim.x * blockDim.x) {
        int j = i;
        if (j < s0) { d_emb[j] = __float2half_rn(emb[j]); continue; }
        j -= s0;
        if (j < s1) {
            int r = j / NC, c = j - r * NC;
            d_c[r * PADC + c] = __float2half_rn(content[j]);
            continue;
        }
        j -= s1;
        if (j < s2) { d_we[j] = __float2half_rn(W_exp[j]); continue; }
        j -= s2;
        if (j < s3) {
            int r = j / NC, c = j - r * NC;
            d_wp1[r * PADC + c] = __float2half_rn(W_p1[j]);
            continue;
        }
        j -= s3;
        if (j < s4) {
            int r = j / NC, c = j - r * NC;
            d_wp2[r * PADC + c] = __float2half_rn(W_p2[j]);
            continue;
        }
        j -= s4;
        if (j < s5) { d_wc[j] = __float2half_rn(W_conv[j]); continue; }
        j -= s5;
        if (j < s6) { d_wo1[j] = __float2half_rn(Wo1[j]); continue; }
        j -= s6;
        d_wo2[j] = __float2half_rn(Wo2[j]);
    }
}

// ---------------------------------------------------------------------------
// CSR build
__global__ void zero_deg_kernel(int n) {
    int i = blockIdx.x * blockDim.x + threadIdx.x;
    if (i < n) g_deg[i] = 0;
}
__global__ void count_deg_kernel(const int* __restrict__ dst, int E) {
    int i = blockIdx.x * blockDim.x + threadIdx.x;
    int stride = gridDim.x * blockDim.x;
    for (; i < E; i += stride) atomicAdd(&g_deg[dst[i]], 1);
}
// phase 1: per-block sums of deg (block = SCAN_B elements)
__global__ void scan_reduce_kernel(int n) {
    __shared__ int ws[32];
    int t = threadIdx.x;
    int i = blockIdx.x * SCAN_B + t;
    int v = (i < n) ? g_deg[i] : 0;
    #pragma unroll
    for (int o = 16; o > 0; o >>= 1) v += __shfl_xor_sync(0xffffffffu, v, o);
    if ((t & 31) == 0) ws[t >> 5] = v;
    __syncthreads();
    if (t < 32) {
        int x = (t < (SCAN_B / 32)) ? ws[t] : 0;
        #pragma unroll
        for (int o = 16; o > 0; o >>= 1) x += __shfl_xor_sync(0xffffffffu, x, o);
        if (t == 0) g_bsum[blockIdx.x] = x;
    }
}
// phase 2: serial exclusive scan of block sums (tiny) + total
__global__ void scan_offsets_kernel(int nb, int n) {
    int acc = 0;
    for (int b = 0; b < nb; b++) { g_boff[b] = acc; acc += g_bsum[b]; }
    g_rowoff[n] = acc;
}
// phase 3: per-block exclusive scan + global offset
__global__ void scan_final_kernel(int n) {
    __shared__ int ws[32];
    int t = threadIdx.x;
    int i = blockIdx.x * SCAN_B + t;
    int v = (i < n) ? g_deg[i] : 0;
    int x = v;
    #pragma unroll
    for (int o = 1; o < 32; o <<= 1) {
        int y = __shfl_up_sync(0xffffffffu, x, o);
        if ((t & 31) >= o) x += y;
    }
    if ((t & 31) == 31) ws[t >> 5] = x;
    __syncthreads();
    if (t < 32) {
        int w = (t < (SCAN_B / 32)) ? ws[t] : 0;
        int xx = w;
        #pragma unroll
        for (int o = 1; o < 32; o <<= 1) {
            int y = __shfl_up_sync(0xffffffffu, xx, o);
            if (t >= o) xx += y;
        }
        ws[t] = xx - w;   // exclusive warp offset
    }
    __syncthreads();
    if (i < n) {
        int excl = x - v + ws[t >> 5] + g_boff[blockIdx.x];
        g_rowoff[i] = excl;
        g_cursor[i] = excl;
    }
}
__global__ void scatter_kernel(const int* __restrict__ src,
                               const int* __restrict__ dst, int E) {
    int i = blockIdx.x * blockDim.x + threadIdx.x;
    int stride = gridDim.x * blockDim.x;
    for (; i < E; i += stride) {
        int p = atomicAdd(&g_cursor[dst[i]], 1);
        g_adj[p] = src[i];
    }
}

// ---------------------------------------------------------------------------
// aggregate: hagg16[n] = fp16(mean of in-neighbor h16); (64,4) block shape,
// thread j owns 4 halves (8B) at col j*4; 4-edge unroll for MLP.
__global__ void aggregate_kernel(int N) {
    int node = blockIdx.x * blockDim.y + threadIdx.y;
    if (node >= N) return;
    int j = threadIdx.x;  // 0..63
    int beg = g_rowoff[node], end = g_rowoff[node + 1];
    float a0 = 0.f, a1 = 0.f, a2 = 0.f, a3 = 0.f;
    int e = beg;
    for (; e + 3 < end; e += 4) {
        int s0 = g_adj[e], s1 = g_adj[e + 1], s2 = g_adj[e + 2], s3 = g_adj[e + 3];
        uint2 u0 = *(const uint2*)&g_h16[(size_t)s0 * FDIM + j * 4];
        uint2 u1 = *(const uint2*)&g_h16[(size_t)s1 * FDIM + j * 4];
        uint2 u2 = *(const uint2*)&g_h16[(size_t)s2 * FDIM + j * 4];
        uint2 u3 = *(const uint2*)&g_h16[(size_t)s3 * FDIM + j * 4];
        float2 p;
        p = __half22float2(*(const __half2*)&u0.x); a0 += p.x; a1 += p.y;
        p = __half22float2(*(const __half2*)&u0.y); a2 += p.x; a3 += p.y;
        p = __half22float2(*(const __half2*)&u1.x); a0 += p.x; a1 += p.y;
        p = __half22float2(*(const __half2*)&u1.y); a2 += p.x; a3 += p.y;
        p = __half22float2(*(const __half2*)&u2.x); a0 += p.x; a1 += p.y;
        p = __half22float2(*(const __half2*)&u2.y); a2 += p.x; a3 += p.y;
        p = __half22float2(*(const __half2*)&u3.x); a0 += p.x; a1 += p.y;
        p = __half22float2(*(const __half2*)&u3.y); a2 += p.x; a3 += p.y;
    }
    for (; e < end; e++) {
        int s0 = g_adj[e];
        uint2 u0 = *(const uint2*)&g_h16[(size_t)s0 * FDIM + j * 4];
        float2 p;
        p = __half22float2(*(const __half2*)&u0.x); a0 += p.x; a1 += p.y;
        p = __half22float2(*(const __half2*)&u0.y); a2 += p.x; a3 += p.y;
    }
    int d = end - beg;
    float inv = 1.0f / (float)(d > 1 ? d : 1);
    uint2 o;
    *(__half2*)&o.x = __floats2half2_rn(a0 * inv, a1 * inv);
    *(__half2*)&o.y = __floats2half2_rn(a2 * inv, a3 * inv);
    *(uint2*)&g_hagg16[(size_t)node * FDIM + j * 4] = o;
}

// L2-normalize rows: fp32 in -> fp16 out
__global__ void l2norm16_kernel(const float* __restrict__ in,
                                __half* __restrict__ out, int N) {
    int n = blockIdx.x;
    int t = threadIdx.x;
    float v = in[(size_t)n * FDIM + t];
    float ss = v * v;
    #pragma unroll
    for (int o = 16; o > 0; o >>= 1) ss += __shfl_xor_sync(0xffffffffu, ss, o);
    __shared__ float ws[8];
    __shared__ float s_tot;
    if ((t & 31) == 0) ws[t >> 5] = ss;
    __syncthreads();
    if (t == 0) {
        float x = 0.f;
        #pragma unroll
        for (int i = 0; i < 8; i++) x += ws[i];
        s_tot = x;
    }
    __syncthreads();
    float norm = sqrtf(s_tot);
    out[(size_t)n * FDIM + t] = __float2half_rn(v / fmaxf(norm, 1e-6f));
}
// L2-normalize rows: fp32 in -> fp32 out (final layer)
__global__ void l2norm_kernel(const float* __restrict__ in,
                              float* __restrict__ out, int N) {
    int n = blockIdx.x;
    int t = threadIdx.x;
    float v = in[(size_t)n * FDIM + t];
    float ss = v * v;
    #pragma unroll
    for (int o = 16; o > 0; o >>= 1) ss += __shfl_xor_sync(0xffffffffu, ss, o);
    __shared__ float ws[8];
    __shared__ float s_tot;
    if ((t & 31) == 0) ws[t >> 5] = ss;
    __syncthreads();
    if (t == 0) {
        float x = 0.f;
        #pragma unroll
        for (int i = 0; i < 8; i++) x += ws[i];
        s_tot = x;
    }
    __syncthreads();
    float norm = sqrtf(s_tot);
    out[(size_t)n * FDIM + t] = v / fmaxf(norm, 1e-6f);
}

// ---------------------------------------------------------------------------
// fp16 GEMM (round 6, unchanged): CTA 128x128, K-chunk 64, 3-stage cp.async,
// XOR-swizzled smem, ldmatrix fragments, mma m16n8k16.
__device__ __forceinline__ void mma_f16(float* c, const uint32_t* a,
                                        const uint32_t* b) {
    asm volatile(
        "mma.sync.aligned.m16n8k16.row.col.f32.f16.f16.f32 "
        "{%0,%1,%2,%3}, {%4,%5,%6,%7}, {%8,%9}, {%0,%1,%2,%3};"
        : "+f"(c[0]), "+f"(c[1]), "+f"(c[2]), "+f"(c[3])
        : "r"(a[0]), "r"(a[1]), "r"(a[2]), "r"(a[3]), "r"(b[0]), "r"(b[1]));
}
__device__ __forceinline__ void ldsm4(uint32_t* r, uint32_t addr) {
    asm volatile("ldmatrix.sync.aligned.m8n8.x4.shared.b16 {%0,%1,%2,%3}, [%4];"
                 : "=r"(r[0]), "=r"(r[1]), "=r"(r[2]), "=r"(r[3]) : "r"(addr));
}
__device__ __forceinline__ void cp16(uint32_t dst, const void* src, int nbytes) {
    asm volatile("cp.async.cg.shared.global [%0], [%1], 16, %2;"
                 :: "r"(dst), "l"(src), "r"(nbytes) : "memory");
}
__device__ __forceinline__ void cp_commit() {
    asm volatile("cp.async.commit_group;" ::: "memory");
}
__device__ __forceinline__ void cp_wait1() {
    asm volatile("cp.async.wait_group 1;" ::: "memory");
}

#define GBM 128
#define GBN 128
#define GBK 64
#define TILE_BYTES 16384
#define STAGE_BYTES (2 * TILE_BYTES)
#define NSTAGE 3

extern __shared__ __align__(16) char sm_raw[];

__global__ __launch_bounds__(256, 2)
void gemm_f16(const __half* __restrict__ A, const __half* __restrict__ A2,
              int kSplit, int lda,
              const int* __restrict__ gidx,
              const __half* __restrict__ W, int ldw,
              const float* __restrict__ bias,
              const float* __restrict__ addsrc,
              float* __restrict__ C, __half* __restrict__ C16, int ldc,
              int M, int Ncols, int K, int act)
{
    const int tid = threadIdx.x;
    const int wid = tid >> 5;
    const int lane = tid & 31;
    const int bm = blockIdx.x * GBM;
    const int bn = blockIdx.y * GBN;
    const int warp_m = (wid >> 2) * 64;
    const int warp_n = (wid & 3) * 32;

    const int ldRow = tid >> 1;
    const int kHalf = tid & 1;

    const bool aValid = (bm + ldRow < M);
    int aR = aValid ? (bm + ldRow) : 0;
    if (gidx) aR = __ldg(&gidx[aValid ? bm + ldRow : 0]);
    const __half* aBase = A + (size_t)aR * lda;
    const __half* aBase2 = A2 ? (A2 + (size_t)aR * lda) : nullptr;
    const bool bValid = (bn + ldRow < Ncols);
    const __half* bBase = W + (size_t)(bValid ? bn + ldRow : 0) * ldw;

    const uint32_t smemBase = (uint32_t)__cvta_generic_to_shared(sm_raw);
    const int nCh = (K + GBK - 1) / GBK;
    const int ldSwz = (ldRow & 7);

    float acc[4][4][4];
    #pragma unroll
    for (int mt = 0; mt < 4; mt++)
        #pragma unroll
        for (int nt = 0; nt < 4; nt++)
            #pragma unroll
            for (int j = 0; j < 4; j++) acc[mt][nt][j] = 0.f;

    auto issueStage = [&](int ch, int stage) {
        if (ch < nCh) {
            const uint32_t aDst = smemBase + stage * STAGE_BYTES + ldRow * 128;
            const uint32_t bDst = aDst + TILE_BYTES;
            #pragma unroll
            for (int j = 0; j < 4; j++) {
                const int c = kHalf * 4 + j;
                const int k = ch * GBK + c * 8;
                const int rem = K - k;
                const int nb = (rem >= 8) ? 16 : (rem > 0 ? rem * 2 : 0);
                const __half* ap = (k < kSplit) ? (aBase + k)
                                                : (aBase2 + (k - kSplit));
                const uint32_t sw = (uint32_t)((c ^ ldSwz) << 4);
                cp16(aDst + sw, ap, aValid ? nb : 0);
                cp16(bDst + sw, bBase + k, bValid ? nb : 0);
            }
        }
        cp_commit();
    };

    const int l8 = lane & 7;
    int aRowB[4], aSwz[4];
    #pragma unroll
    for (int mt = 0; mt < 4; mt++) {
        int row = warp_m + mt * 16 + l8 + ((lane >> 3) & 1) * 8;
        aRowB[mt] = row * 128;
        aSwz[mt] = row & 7;
    }
    const int aColAdd = lane >> 4;
    int bRowB[2], bSwz[2];
    #pragma unroll
    for (int pr = 0; pr < 2; pr++) {
        int row = warp_n + pr * 16 + l8 + ((lane >> 4) & 1) * 8;
        bRowB[pr] = row * 128;
        bSwz[pr] = row & 7;
    }
    const int bColAdd = (lane >> 3) & 1;

    auto computeStage = [&](int stage) {
        const uint32_t aTile = smemBase + stage * STAGE_BYTES;
        const uint32_t bTile = aTile + TILE_BYTES;
        #pragma unroll
        for (int ks = 0; ks < 4; ks++) {
            uint32_t af[4][4], bf[4][2];
            const int colA = ks * 2 + aColAdd;
            #pragma unroll
            for (int mt = 0; mt < 4; mt++)
                ldsm4(af[mt], aTile + aRowB[mt] + ((colA ^ aSwz[mt]) << 4));
            const int colB = ks * 2 + bColAdd;
            #pragma unroll
            for (int pr = 0; pr < 2; pr++) {
                uint32_t r[4];
                ldsm4(r, bTile + bRowB[pr] + ((colB ^ bSwz[pr]) << 4));
                bf[2 * pr][0] = r[0]; bf[2 * pr][1] = r[1];
                bf[2 * pr + 1][0] = r[2]; bf[2 * pr + 1][1] = r[3];
            }
            #pragma unroll
            for (int mt = 0; mt < 4; mt++)
                #pragma unroll
                for (int nt = 0; nt < 4; nt++)
                    mma_f16(acc[mt][nt], af[mt], bf[nt]);
        }
    };

    issueStage(0, 0);
    issueStage(1, 1);
    for (int ch = 0; ch < nCh; ch++) {
        cp_wait1();
        __syncthreads();
        computeStage(ch % NSTAGE);
        issueStage(ch + 2, (ch + 2) % NSTAGE);
    }

    #pragma unroll
    for (int mt = 0; mt < 4; mt++) {
        int row = bm + warp_m + mt * 16 + (lane >> 2);
        #pragma unroll
        for (int nt = 0; nt < 4; nt++) {
            int col = bn + warp_n + nt * 8 + 2 * (lane & 3);
            if (col >= Ncols) continue;
            float b0 = __ldg(&bias[col]);
            float b1 = __ldg(&bias[col + 1]);
            #pragma unroll
            for (int half = 0; half < 2; half++) {
                int r = row + half * 8;
                if (r >= M) continue;
                float v0 = acc[mt][nt][half * 2 + 0] + b0;
                float v1 = acc[mt][nt][half * 2 + 1] + b1;
                if (act) {
                    v0 = (v0 > 0.f) ? v0 : 0.1f * v0;
                    v1 = (v1 > 0.f) ? v1 : 0.1f * v1;
                }
                if (addsrc) {
                    const float2 s = *(const float2*)&addsrc[(size_t)r * ldc + col];
                    v0 += s.x; v1 += s.y;
                }
                if (C)
                    *(float2*)&C[(size_t)r * ldc + col] = make_float2(v0, v1);
                if (C16)
                    *(__half2*)&C16[(size_t)r * ldc + col] =
                        __floats2half2_rn(v0, v1);
            }
        }
    }
}

// ---------------------------------------------------------------------------
extern "C" void kernel_launch(void* const* d_in, const int* in_sizes, int n_in,
                              void* d_out, int out_size) {
    const int*   node_ids = (const int*)  d_in[0];
    const float* content  = (const float*)d_in[1];
    const int*   src      = (const int*)  d_in[2];
    const int*   dst      = (const int*)  d_in[3];
    const float* emb      = (const float*)d_in[4];
    const float* W_exp    = (const float*)d_in[5];
    const float* b_exp    = (const float*)d_in[6];
    const float* W_p1     = (const float*)d_in[7];
    const float* b_p1     = (const float*)d_in[8];
    const float* W_p2     = (const float*)d_in[9];
    const float* b_p2     = (const float*)d_in[10];
    const float* W_conv   = (const float*)d_in[11];
    const float* b_conv   = (const float*)d_in[12];
    const float* Wo1      = (const float*)d_in[13];
    const float* bo1      = (const float*)d_in[14];
    const float* Wo2      = (const float*)d_in[15];
    const float* bo2      = (const float*)d_in[16];
    float* out = (float*)d_out;

    const int N  = in_sizes[0];
    const int E  = in_sizes[2];
    const int NC = in_sizes[1] / N;                 // 300
    const int ED = in_sizes[4] / (N + 1);           // 64
    const int F  = in_sizes[5] / ED;                // 256
    const int L  = in_sizes[11] / (F * 2 * F);      // 3

    float *p_h, *p_hn;
    __half *p_h16, *p_hn16, *p_hagg16, *p_tmp16, *p_emb16, *p_c16;
    __half *p_we, *p_wp1, *p_wp2, *p_wc, *p_wo1, *p_wo2;
    cudaGetSymbolAddress((void**)&p_h, g_h);
    cudaGetSymbolAddress((void**)&p_hn, g_hn);
    cudaGetSymbolAddress((void**)&p_h16, g_h16);
    cudaGetSymbolAddress((void**)&p_hn16, g_hn16);
    cudaGetSymbolAddress((void**)&p_hagg16, g_hagg16);
    cudaGetSymbolAddress((void**)&p_tmp16, g_tmp16);
    cudaGetSymbolAddress((void**)&p_emb16, g_emb16);
    cudaGetSymbolAddress((void**)&p_c16, g_c16);
    cudaGetSymbolAddress((void**)&p_we, g_we16);
    cudaGetSymbolAddress((void**)&p_wp1, g_wp1);
    cudaGetSymbolAddress((void**)&p_wp2, g_wp2);
    cudaGetSymbolAddress((void**)&p_wc, g_wc16);
    cudaGetSymbolAddress((void**)&p_wo1, g_wo1);
    cudaGetSymbolAddress((void**)&p_wo2, g_wo2);

    const int SMEM = NSTAGE * STAGE_BYTES;  // 98304
    cudaFuncSetAttribute(gemm_f16, cudaFuncAttributeMaxDynamicSharedMemorySize, SMEM);

    // ---- conversions (one kernel) ----
    cvt_all_kernel<<<2048, 256>>>(emb, content, W_exp, W_p1, W_p2, W_conv,
                                  Wo1, Wo2, p_emb16, p_c16, p_we, p_wp1,
                                  p_wp2, p_wc, p_wo1, p_wo2, N, NC, ED, F, L);

    // ---- CSR build (parallel scan) ----
    const int nb = (N + SCAN_B - 1) / SCAN_B;   // 49
    zero_deg_kernel<<<(N + 255) / 256, 256>>>(N);
    count_deg_kernel<<<1024, 256>>>(dst, E);
    scan_reduce_kernel<<<nb, SCAN_B>>>(N);
    scan_offsets_kernel<<<1, 1>>>(nb, N);
    scan_final_kernel<<<nb, SCAN_B>>>(N);
    scatter_kernel<<<1024, 256>>>(src, dst, E);

    const int gmx = (N + GBM - 1) / GBM;
    auto gy = [](int n) { return (n + GBN - 1) / GBN; };
    const int KBIG = 1 << 30;

    // ---- initial representation ----
    gemm_f16<<<dim3(gmx, gy(F)), 256, SMEM>>>(
        p_emb16, nullptr, KBIG, ED, node_ids, p_we, ED, b_exp, nullptr,
        p_h, nullptr, F, N, F, ED, 1);
    gemm_f16<<<dim3(gmx, gy(NC)), 256, SMEM>>>(
        p_c16, nullptr, KBIG, PADC, nullptr, p_wp1, PADC, b_p1, nullptr,
        nullptr, p_tmp16, PADC, N, NC, PADC, 1);
    gemm_f16<<<dim3(gmx, gy(F)), 256, SMEM>>>(
        p_tmp16, nullptr, KBIG, PADC, nullptr, p_wp2, PADC, b_p2, p_h,
        nullptr, p_h16, F, N, F, PADC, 1);

    // ---- layers ----
    for (int i = 0; i < L; i++) {
        dim3 aggBlk(64, 4);
        aggregate_kernel<<<(N + 3) / 4, aggBlk>>>(N);

        int act = (i < L - 1) ? 1 : 0;
        gemm_f16<<<dim3(gmx, gy(F)), 256, SMEM>>>(
            p_h16, p_hagg16, F, F, nullptr,
            p_wc + (size_t)i * F * 2 * F, 2 * F,
            b_conv + (size_t)i * F, nullptr,
            p_hn, nullptr, F, N, F, 2 * F, act);

        if (i < L - 1) {
            l2norm16_kernel<<<N, F>>>(p_hn, p_hn16, N);
            gemm_f16<<<dim3(gmx, gy(F)), 256, SMEM>>>(
                p_hn16, nullptr, KBIG, F, nullptr,
                p_wo1 + (size_t)i * F * F, F,
                bo1 + (size_t)i * F, nullptr,
                nullptr, p_tmp16, F, N, F, F, 1);
            gemm_f16<<<dim3(gmx, gy(F)), 256, SMEM>>>(
                p_tmp16, nullptr, KBIG, F, nullptr,
                p_wo2 + (size_t)i * F * F, F,
                bo2 + (size_t)i * F, nullptr,
                nullptr, p_h16, F, N, F, F, 0);
        } else {
            l2norm_kernel<<<N, F>>>(p_hn, out, N);
        }
    }
}